// round 9
// baseline (speedup 1.0000x reference)
#include <cuda_runtime.h>
#include <cuda_fp16.h>
#include <cuda_bf16.h>
#include <cstdint>

#define NN   8192
#define FIN  256
#define FOUT 128

// ---------------- device scratch ----------------
__device__ __half g_hh[NN * FOUT];     // h fp16, row-major [j][f]
__device__ float  g_fs2[NN];           // f_src * log2(e)
__device__ float  g_fd2[NN];           // f_dst * log2(e)
__device__ int    g_gmax_o = (int)0x80000000;  // ordered-int max of g_fd2 (idempotent)

__device__ __forceinline__ int f2o(float f) {
    int i = __float_as_int(f);
    return i >= 0 ? i : (i ^ 0x7fffffff);
}
__device__ __forceinline__ float o2f(int o) {
    return __int_as_float(o >= 0 ? o : (o ^ 0x7fffffff));
}

#define CP_ASYNC16(dst_u32, src_ptr) \
    asm volatile("cp.async.cg.shared.global [%0], [%1], 16;\n" :: "r"(dst_u32), "l"(src_ptr))

__device__ __forceinline__ void mbar_init(uint32_t addr, uint32_t cnt) {
    asm volatile("mbarrier.init.shared.b64 [%0], %1;\n" :: "r"(addr), "r"(cnt) : "memory");
}
__device__ __forceinline__ void mbar_arrive(uint32_t addr) {
    asm volatile("mbarrier.arrive.shared.b64 _, [%0];\n" :: "r"(addr) : "memory");
}
__device__ __forceinline__ void mbar_wait(uint32_t addr, uint32_t parity) {
    asm volatile(
        "{\n\t.reg .pred P;\n"
        "W_%=:\n\t"
        "mbarrier.try_wait.parity.acquire.cta.shared::cta.b64 P, [%0], %1, 0x989680;\n\t"
        "@P bra D_%=;\n\t"
        "bra W_%=;\n"
        "D_%=:\n\t}"
        :: "r"(addr), "r"(parity) : "memory");
}

#define MMA16816(C0, C1, C2, C3, A0, A1, A2, A3, B0, B1) \
    asm volatile( \
        "mma.sync.aligned.m16n8k16.row.col.f32.f16.f16.f32 " \
        "{%0,%1,%2,%3}, {%4,%5,%6,%7}, {%8,%9}, {%0,%1,%2,%3};\n" \
        : "+f"(C0), "+f"(C1), "+f"(C2), "+f"(C3) \
        : "r"(A0), "r"(A1), "r"(A2), "r"(A3), "r"(B0), "r"(B1))

// ---------------- kernel 1: h = x @ W (fp16 MMA, inline cvt) -------------
#define SMEM_GEMM 103424

__global__ __launch_bounds__(128, 1) void k_gemm(
    const float* __restrict__ x, const float* __restrict__ W,
    const float* __restrict__ a_src, const float* __restrict__ a_dst)
{
    extern __shared__ char smem[];
    __half* sX = (__half*)smem;
    __half* sW = (__half*)(smem + 33792);
    const uint32_t sb = (uint32_t)__cvta_generic_to_shared(smem);

    const int tid = threadIdx.x;
    const int lane = tid & 31, wid = tid >> 5;
    const int i0 = blockIdx.x * 64;

    #pragma unroll
    for (int l = 0; l < 16; l++) {
        int idx = tid + l * 128;
        int row = idx >> 5, c8 = (idx & 31) << 3;
        const float4* src = (const float4*)&x[(size_t)(i0 + row) * FIN + c8];
        float4 v0 = src[0], v1 = src[1];
        __half2 h0 = __floats2half2_rn(v0.x, v0.y);
        __half2 h1 = __floats2half2_rn(v0.z, v0.w);
        __half2 h2 = __floats2half2_rn(v1.x, v1.y);
        __half2 h3 = __floats2half2_rn(v1.z, v1.w);
        uint4 pk; pk.x = *(uint32_t*)&h0; pk.y = *(uint32_t*)&h1;
        pk.z = *(uint32_t*)&h2; pk.w = *(uint32_t*)&h3;
        *(uint4*)&sX[row * 264 + c8] = pk;
    }
    #pragma unroll
    for (int l = 0; l < 32; l++) {
        int idx = tid + l * 128;
        int row = idx >> 4, c8 = (idx & 15) << 3;
        const float4* src = (const float4*)&W[(size_t)row * FOUT + c8];
        float4 v0 = src[0], v1 = src[1];
        __half2 h0 = __floats2half2_rn(v0.x, v0.y);
        __half2 h1 = __floats2half2_rn(v0.z, v0.w);
        __half2 h2 = __floats2half2_rn(v1.x, v1.y);
        __half2 h3 = __floats2half2_rn(v1.z, v1.w);
        uint4 pk; pk.x = *(uint32_t*)&h0; pk.y = *(uint32_t*)&h1;
        pk.z = *(uint32_t*)&h2; pk.w = *(uint32_t*)&h3;
        *(uint4*)&sW[row * 136 + c8] = pk;
    }
    __syncthreads();

    float C[16][4];
    #pragma unroll
    for (int a = 0; a < 16; a++)
        #pragma unroll
        for (int b = 0; b < 4; b++) C[a][b] = 0.f;

    const int wm = wid * 16;
    const uint32_t aB = sb + ((wm + (lane & 15)) * 264 + ((lane >> 4) << 3)) * 2;
    const uint32_t bB = sb + 33792 + (((lane & 15)) * 136 + ((lane >> 4) << 3)) * 2;

    #pragma unroll
    for (int kc = 0; kc < 16; kc++) {
        uint32_t a0, a1, a2, a3;
        asm volatile("ldmatrix.sync.aligned.m8n8.x4.shared.b16 {%0,%1,%2,%3},[%4];\n"
                     : "=r"(a0), "=r"(a1), "=r"(a2), "=r"(a3) : "r"(aB + kc * 32));
        #pragma unroll
        for (int nt = 0; nt < 8; nt++) {
            uint32_t b0, b1, b2, b3;
            asm volatile("ldmatrix.sync.aligned.m8n8.x4.trans.shared.b16 {%0,%1,%2,%3},[%4];\n"
                         : "=r"(b0), "=r"(b1), "=r"(b2), "=r"(b3)
                         : "r"(bB + kc * 16 * 272 + nt * 32));
            MMA16816(C[2*nt][0], C[2*nt][1], C[2*nt][2], C[2*nt][3],
                     a0, a1, a2, a3, b0, b1);
            MMA16816(C[2*nt+1][0], C[2*nt+1][1], C[2*nt+1][2], C[2*nt+1][3],
                     a0, a1, a2, a3, b2, b3);
        }
    }

    const int g = lane >> 2, q = lane & 3;
    const int r0 = wm + g, r1 = r0 + 8;
    float ds0 = 0.f, dd0 = 0.f, ds1 = 0.f, dd1 = 0.f;
    #pragma unroll
    for (int nt = 0; nt < 16; nt++) {
        int col = nt * 8 + q * 2;
        float as0 = __ldg(a_src + col), as1 = __ldg(a_src + col + 1);
        float ad0 = __ldg(a_dst + col), ad1 = __ldg(a_dst + col + 1);
        ds0 += C[nt][0] * as0 + C[nt][1] * as1;
        dd0 += C[nt][0] * ad0 + C[nt][1] * ad1;
        ds1 += C[nt][2] * as0 + C[nt][3] * as1;
        dd1 += C[nt][2] * ad0 + C[nt][3] * ad1;
        __half2 h0 = __floats2half2_rn(C[nt][0], C[nt][1]);
        __half2 h1 = __floats2half2_rn(C[nt][2], C[nt][3]);
        *(uint32_t*)&g_hh[(size_t)(i0 + r0) * FOUT + col] = *(uint32_t*)&h0;
        *(uint32_t*)&g_hh[(size_t)(i0 + r1) * FOUT + col] = *(uint32_t*)&h1;
    }
    ds0 += __shfl_xor_sync(0xffffffffu, ds0, 1); ds0 += __shfl_xor_sync(0xffffffffu, ds0, 2);
    dd0 += __shfl_xor_sync(0xffffffffu, dd0, 1); dd0 += __shfl_xor_sync(0xffffffffu, dd0, 2);
    ds1 += __shfl_xor_sync(0xffffffffu, ds1, 1); ds1 += __shfl_xor_sync(0xffffffffu, ds1, 2);
    dd1 += __shfl_xor_sync(0xffffffffu, dd1, 1); dd1 += __shfl_xor_sync(0xffffffffu, dd1, 2);
    if (q == 0) {
        const float L2E = 1.4426950408889634f;
        g_fs2[i0 + r0] = ds0 * L2E; g_fd2[i0 + r0] = dd0 * L2E;
        g_fs2[i0 + r1] = ds1 * L2E; g_fd2[i0 + r1] = dd1 * L2E;
        atomicMax(&g_gmax_o, f2o(dd0 * L2E));
        atomicMax(&g_gmax_o, f2o(dd1 * L2E));
    }
}

// ---------------- kernel 2: warp-specialized fused attention ---------------
// grid 128 (64-row i-tiles), block 512:
//   warps 0-7  consume: 2 row-groups x 4 col-groups, each 32 rows x 32 cols
//   warps 8-15 produce: each owns 8 P-rows
// 3-STAGE pipeline. Stage block = [sH 128x136 half (34816B) | sP 64x136 half (17408B)]
//   stage s at s*52224;  sDen @156672 (64 f32);  mbF @156928 (3x8);  mbE @156952
#define STG      52224
#define OFF_DEN  156672
#define OFF_MBF  156928
#define OFF_MBE  156952
#define SMEM_MAIN 157056

__global__ __launch_bounds__(512, 1) void k_main(
    const float* __restrict__ adj, float* __restrict__ out)
{
    extern __shared__ char smem[];
    const uint32_t sb = (uint32_t)__cvta_generic_to_shared(smem);
    float* sDen = (float*)(smem + OFF_DEN);
    const uint32_t mbF = sb + OFF_MBF;
    const uint32_t mbE = sb + OFF_MBE;

    const int tid = threadIdx.x;
    const int lane = tid & 31, wid = tid >> 5;
    const int i0 = blockIdx.x * 64;

    if (tid == 0) {
        #pragma unroll
        for (int s = 0; s < 3; s++) {
            mbar_init(mbF + s * 8, 256);
            mbar_init(mbE + s * 8, 256);
        }
    }
    __syncthreads();

    float C[8][4];

    if (wid >= 8) {
        // ---------------- producer: 8 rows per warp ----------------
        const int p = wid - 8;               // 0..7
        const int pt = tid - 256;            // 0..255
        const float gmax2 = o2f(g_gmax_o);
        float fs[8], m2[8], den[8];
        #pragma unroll
        for (int rr = 0; rr < 8; rr++) {
            float f = g_fs2[i0 + p * 8 + rr];
            fs[rr] = f;
            float sm = f + gmax2;
            m2[rr] = (sm >= 0.f) ? sm : 0.2f * sm;
            den[rr] = 0.f;
        }
        const float* adjB = adj + (size_t)(i0 + p * 8) * NN + (lane << 2);

        uint32_t pe0 = 1, pe1 = 1, pe2 = 1;
        int st = 0;
        for (int jt = 0; jt < 64; jt++) {
            const int j0 = jt << 7;

            // hoist loads (latency overlapped with empty-wait)
            float4 av[8];
            const float* arow = adjB + j0;
            #pragma unroll
            for (int rr = 0; rr < 8; rr++)
                av[rr] = __ldcs((const float4*)(arow + (size_t)rr * NN));
            float4 fd = __ldg((const float4*)(g_fd2 + j0 + (lane << 2)));

            uint32_t pe = (st == 0) ? pe0 : (st == 1) ? pe1 : pe2;
            mbar_wait(mbE + st * 8, pe);
            if (st == 0) pe0 ^= 1; else if (st == 1) pe1 ^= 1; else pe2 ^= 1;

            // async-load H tile into stage st
            const __half* hsrc = g_hh + (size_t)j0 * FOUT;
            const uint32_t hdst = sb + st * STG;
            #pragma unroll
            for (int l = 0; l < 8; l++) {
                int idx = pt + (l << 8);
                int row = idx >> 4, c8 = idx & 15;
                CP_ASYNC16(hdst + (row * 136 + c8 * 8) * 2, hsrc + row * FOUT + c8 * 8);
            }
            asm volatile("cp.async.commit_group;\n" ::: "memory");

            // P tile rows p*8..+8, cols lane*4..+4 -> fp16 smem
            float fdv[4] = {fd.x, fd.y, fd.z, fd.w};
            __half* sPs = (__half*)(smem + st * STG + 34816) + p * 8 * 136 + (lane << 2);
            #pragma unroll
            for (int rr = 0; rr < 8; rr++) {
                float p4[4];
                const float* aa = (const float*)&av[rr];
                #pragma unroll
                for (int u = 0; u < 4; u++) {
                    float s2 = fs[rr] + fdv[u];
                    float t = ((s2 >= 0.f) ? s2 : 0.2f * s2) - m2[rr];
                    float e;
                    asm("ex2.approx.ftz.f32 %0, %1;" : "=f"(e) : "f"(t));
                    p4[u] = (aa[u] > 0.f) ? e : 0.f;
                    den[rr] += p4[u];
                }
                __half2 h01 = __floats2half2_rn(p4[0], p4[1]);
                __half2 h23 = __floats2half2_rn(p4[2], p4[3]);
                uint2 pk; pk.x = *(uint32_t*)&h01; pk.y = *(uint32_t*)&h23;
                *(uint2*)(sPs + rr * 136) = pk;
            }

            asm volatile("cp.async.wait_group 0;\n" ::: "memory");
            mbar_arrive(mbF + st * 8);
            st = (st == 2) ? 0 : st + 1;
        }
        // reduce denominators across lanes
        #pragma unroll
        for (int rr = 0; rr < 8; rr++) {
            float v = den[rr];
            #pragma unroll
            for (int o = 1; o < 32; o <<= 1) v += __shfl_xor_sync(0xffffffffu, v, o);
            if (lane == 0) sDen[p * 8 + rr] = v;
        }
    } else {
        // ---------------- consumer: 32 rows x 32 cols per warp (2x4 grid) ----
        #pragma unroll
        for (int a = 0; a < 8; a++)
            #pragma unroll
            for (int b = 0; b < 4; b++) C[a][b] = 0.f;

        const int wm = (wid & 1) * 32;    // 2 row-groups of 32
        const int wn = (wid >> 1) * 32;   // 4 col-groups of 32

        uint32_t pf0 = 0, pf1 = 0, pf2 = 0;
        int st = 0;
        for (int jt = 0; jt < 64; jt++) {
            uint32_t pf = (st == 0) ? pf0 : (st == 1) ? pf1 : pf2;
            mbar_wait(mbF + st * 8, pf);
            if (st == 0) pf0 ^= 1; else if (st == 1) pf1 ^= 1; else pf2 ^= 1;

            const uint32_t aB = sb + st * STG + 34816 +
                ((wm + (lane & 15)) * 136 + ((lane >> 4) << 3)) * 2;
            const uint32_t bB = sb + st * STG +
                ((lane & 15) * 136 + wn + ((lane >> 4) << 3)) * 2;

            #pragma unroll
            for (int kk = 0; kk < 8; kk++) {
                uint32_t a0[4], a1[4];
                asm volatile("ldmatrix.sync.aligned.m8n8.x4.shared.b16 {%0,%1,%2,%3},[%4];\n"
                             : "=r"(a0[0]), "=r"(a0[1]), "=r"(a0[2]), "=r"(a0[3])
                             : "r"(aB + kk * 32));
                asm volatile("ldmatrix.sync.aligned.m8n8.x4.shared.b16 {%0,%1,%2,%3},[%4];\n"
                             : "=r"(a1[0]), "=r"(a1[1]), "=r"(a1[2]), "=r"(a1[3])
                             : "r"(aB + 16 * 272 + kk * 32));
                #pragma unroll
                for (int nt = 0; nt < 2; nt++) {
                    uint32_t b0, b1, b2, b3;
                    asm volatile("ldmatrix.sync.aligned.m8n8.x4.trans.shared.b16 {%0,%1,%2,%3},[%4];\n"
                                 : "=r"(b0), "=r"(b1), "=r"(b2), "=r"(b3)
                                 : "r"(bB + kk * 16 * 272 + nt * 32));
                    MMA16816(C[nt*2][0], C[nt*2][1], C[nt*2][2], C[nt*2][3],
                             a0[0], a0[1], a0[2], a0[3], b0, b1);
                    MMA16816(C[nt*2+1][0], C[nt*2+1][1], C[nt*2+1][2], C[nt*2+1][3],
                             a0[0], a0[1], a0[2], a0[3], b2, b3);
                    MMA16816(C[4+nt*2][0], C[4+nt*2][1], C[4+nt*2][2], C[4+nt*2][3],
                             a1[0], a1[1], a1[2], a1[3], b0, b1);
                    MMA16816(C[4+nt*2+1][0], C[4+nt*2+1][1], C[4+nt*2+1][2], C[4+nt*2+1][3],
                             a1[0], a1[1], a1[2], a1[3], b2, b3);
                }
            }
            mbar_arrive(mbE + st * 8);
            st = (st == 2) ? 0 : st + 1;
        }
    }

    __syncthreads();

    if (wid < 8) {
        const int wm = (wid & 1) * 32;
        const int wn = (wid >> 1) * 32;
        const int g = lane >> 2, q = lane & 3;
        #pragma unroll
        for (int mt = 0; mt < 2; mt++) {
            const int r0 = wm + mt * 16 + g;
            const int r1 = r0 + 8;
            const float inv0 = 1.f / sDen[r0];
            const float inv1 = 1.f / sDen[r1];
            #pragma unroll
            for (int nt = 0; nt < 4; nt++) {
                const float* frag = C[mt * 4 + nt];
                int col = wn + nt * 8 + q * 2;
                float* o0 = &out[(size_t)(i0 + r0) * FOUT + col];
                o0[0] = frag[0] * inv0;
                o0[1] = frag[1] * inv0;
                float* o1 = &out[(size_t)(i0 + r1) * FOUT + col];
                o1[0] = frag[2] * inv1;
                o1[1] = frag[3] * inv1;
            }
        }
    }
}

// ---------------- launcher ----------------
extern "C" void kernel_launch(void* const* d_in, const int* in_sizes, int n_in,
                              void* d_out, int out_size)
{
    const float* x     = (const float*)d_in[0];
    const float* adj   = (const float*)d_in[1];
    const float* W     = (const float*)d_in[2];
    const float* a_src = (const float*)d_in[3];
    const float* a_dst = (const float*)d_in[4];
    float* out = (float*)d_out;

    cudaFuncSetAttribute(k_gemm, cudaFuncAttributeMaxDynamicSharedMemorySize, SMEM_GEMM);
    cudaFuncSetAttribute(k_main, cudaFuncAttributeMaxDynamicSharedMemorySize, SMEM_MAIN);

    k_gemm<<<128, 128, SMEM_GEMM>>>(x, W, a_src, a_dst);
    k_main<<<128, 512, SMEM_MAIN>>>(adj, out);
}

// round 10
// speedup vs baseline: 1.2062x; 1.2062x over previous
#include <cuda_runtime.h>
#include <cuda_fp16.h>
#include <cuda_bf16.h>
#include <cstdint>

#define NN   8192
#define FIN  256
#define FOUT 128

// ---------------- device scratch ----------------
__device__ __half g_hh[NN * FOUT];     // h fp16, row-major [j][f]
__device__ float  g_fs2[NN];           // f_src * log2(e)
__device__ float  g_fd2[NN];           // f_dst * log2(e)
__device__ int    g_gmax_o = (int)0x80000000;  // ordered-int max of g_fd2 (idempotent)

__device__ __forceinline__ int f2o(float f) {
    int i = __float_as_int(f);
    return i >= 0 ? i : (i ^ 0x7fffffff);
}
__device__ __forceinline__ float o2f(int o) {
    return __int_as_float(o >= 0 ? o : (o ^ 0x7fffffff));
}

#define CP_ASYNC16(dst_u32, src_ptr) \
    asm volatile("cp.async.cg.shared.global [%0], [%1], 16;\n" :: "r"(dst_u32), "l"(src_ptr))

__device__ __forceinline__ void mbar_init(uint32_t addr, uint32_t cnt) {
    asm volatile("mbarrier.init.shared.b64 [%0], %1;\n" :: "r"(addr), "r"(cnt) : "memory");
}
__device__ __forceinline__ void mbar_arrive(uint32_t addr) {
    asm volatile("mbarrier.arrive.shared.b64 _, [%0];\n" :: "r"(addr) : "memory");
}
// async arrive: fires on this thread's prior cp.async completion (no expect-count bump)
__device__ __forceinline__ void mbar_arrive_cpasync(uint32_t addr) {
    asm volatile("cp.async.mbarrier.arrive.noinc.shared.b64 [%0];\n" :: "r"(addr) : "memory");
}
__device__ __forceinline__ void mbar_wait(uint32_t addr, uint32_t parity) {
    asm volatile(
        "{\n\t.reg .pred P;\n"
        "W_%=:\n\t"
        "mbarrier.try_wait.parity.acquire.cta.shared::cta.b64 P, [%0], %1, 0x989680;\n\t"
        "@P bra D_%=;\n\t"
        "bra W_%=;\n"
        "D_%=:\n\t}"
        :: "r"(addr), "r"(parity) : "memory");
}

#define MMA16816(C0, C1, C2, C3, A0, A1, A2, A3, B0, B1) \
    asm volatile( \
        "mma.sync.aligned.m16n8k16.row.col.f32.f16.f16.f32 " \
        "{%0,%1,%2,%3}, {%4,%5,%6,%7}, {%8,%9}, {%0,%1,%2,%3};\n" \
        : "+f"(C0), "+f"(C1), "+f"(C2), "+f"(C3) \
        : "r"(A0), "r"(A1), "r"(A2), "r"(A3), "r"(B0), "r"(B1))

// ---------------- kernel 1: h = x @ W (fp16 MMA, inline cvt) -------------
#define SMEM_GEMM 103424

__global__ __launch_bounds__(128, 1) void k_gemm(
    const float* __restrict__ x, const float* __restrict__ W,
    const float* __restrict__ a_src, const float* __restrict__ a_dst)
{
    extern __shared__ char smem[];
    __half* sX = (__half*)smem;
    __half* sW = (__half*)(smem + 33792);
    const uint32_t sb = (uint32_t)__cvta_generic_to_shared(smem);

    const int tid = threadIdx.x;
    const int lane = tid & 31, wid = tid >> 5;
    const int i0 = blockIdx.x * 64;

    #pragma unroll
    for (int l = 0; l < 16; l++) {
        int idx = tid + l * 128;
        int row = idx >> 5, c8 = (idx & 31) << 3;
        const float4* src = (const float4*)&x[(size_t)(i0 + row) * FIN + c8];
        float4 v0 = src[0], v1 = src[1];
        __half2 h0 = __floats2half2_rn(v0.x, v0.y);
        __half2 h1 = __floats2half2_rn(v0.z, v0.w);
        __half2 h2 = __floats2half2_rn(v1.x, v1.y);
        __half2 h3 = __floats2half2_rn(v1.z, v1.w);
        uint4 pk; pk.x = *(uint32_t*)&h0; pk.y = *(uint32_t*)&h1;
        pk.z = *(uint32_t*)&h2; pk.w = *(uint32_t*)&h3;
        *(uint4*)&sX[row * 264 + c8] = pk;
    }
    #pragma unroll
    for (int l = 0; l < 32; l++) {
        int idx = tid + l * 128;
        int row = idx >> 4, c8 = (idx & 15) << 3;
        const float4* src = (const float4*)&W[(size_t)row * FOUT + c8];
        float4 v0 = src[0], v1 = src[1];
        __half2 h0 = __floats2half2_rn(v0.x, v0.y);
        __half2 h1 = __floats2half2_rn(v0.z, v0.w);
        __half2 h2 = __floats2half2_rn(v1.x, v1.y);
        __half2 h3 = __floats2half2_rn(v1.z, v1.w);
        uint4 pk; pk.x = *(uint32_t*)&h0; pk.y = *(uint32_t*)&h1;
        pk.z = *(uint32_t*)&h2; pk.w = *(uint32_t*)&h3;
        *(uint4*)&sW[row * 136 + c8] = pk;
    }
    __syncthreads();

    float C[16][4];
    #pragma unroll
    for (int a = 0; a < 16; a++)
        #pragma unroll
        for (int b = 0; b < 4; b++) C[a][b] = 0.f;

    const int wm = wid * 16;
    const uint32_t aB = sb + ((wm + (lane & 15)) * 264 + ((lane >> 4) << 3)) * 2;
    const uint32_t bB = sb + 33792 + (((lane & 15)) * 136 + ((lane >> 4) << 3)) * 2;

    #pragma unroll
    for (int kc = 0; kc < 16; kc++) {
        uint32_t a0, a1, a2, a3;
        asm volatile("ldmatrix.sync.aligned.m8n8.x4.shared.b16 {%0,%1,%2,%3},[%4];\n"
                     : "=r"(a0), "=r"(a1), "=r"(a2), "=r"(a3) : "r"(aB + kc * 32));
        #pragma unroll
        for (int nt = 0; nt < 8; nt++) {
            uint32_t b0, b1, b2, b3;
            asm volatile("ldmatrix.sync.aligned.m8n8.x4.trans.shared.b16 {%0,%1,%2,%3},[%4];\n"
                         : "=r"(b0), "=r"(b1), "=r"(b2), "=r"(b3)
                         : "r"(bB + kc * 16 * 272 + nt * 32));
            MMA16816(C[2*nt][0], C[2*nt][1], C[2*nt][2], C[2*nt][3],
                     a0, a1, a2, a3, b0, b1);
            MMA16816(C[2*nt+1][0], C[2*nt+1][1], C[2*nt+1][2], C[2*nt+1][3],
                     a0, a1, a2, a3, b2, b3);
        }
    }

    const int g = lane >> 2, q = lane & 3;
    const int r0 = wm + g, r1 = r0 + 8;
    float ds0 = 0.f, dd0 = 0.f, ds1 = 0.f, dd1 = 0.f;
    #pragma unroll
    for (int nt = 0; nt < 16; nt++) {
        int col = nt * 8 + q * 2;
        float as0 = __ldg(a_src + col), as1 = __ldg(a_src + col + 1);
        float ad0 = __ldg(a_dst + col), ad1 = __ldg(a_dst + col + 1);
        ds0 += C[nt][0] * as0 + C[nt][1] * as1;
        dd0 += C[nt][0] * ad0 + C[nt][1] * ad1;
        ds1 += C[nt][2] * as0 + C[nt][3] * as1;
        dd1 += C[nt][2] * ad0 + C[nt][3] * ad1;
        __half2 h0 = __floats2half2_rn(C[nt][0], C[nt][1]);
        __half2 h1 = __floats2half2_rn(C[nt][2], C[nt][3]);
        *(uint32_t*)&g_hh[(size_t)(i0 + r0) * FOUT + col] = *(uint32_t*)&h0;
        *(uint32_t*)&g_hh[(size_t)(i0 + r1) * FOUT + col] = *(uint32_t*)&h1;
    }
    ds0 += __shfl_xor_sync(0xffffffffu, ds0, 1); ds0 += __shfl_xor_sync(0xffffffffu, ds0, 2);
    dd0 += __shfl_xor_sync(0xffffffffu, dd0, 1); dd0 += __shfl_xor_sync(0xffffffffu, dd0, 2);
    ds1 += __shfl_xor_sync(0xffffffffu, ds1, 1); ds1 += __shfl_xor_sync(0xffffffffu, ds1, 2);
    dd1 += __shfl_xor_sync(0xffffffffu, dd1, 1); dd1 += __shfl_xor_sync(0xffffffffu, dd1, 2);
    if (q == 0) {
        const float L2E = 1.4426950408889634f;
        g_fs2[i0 + r0] = ds0 * L2E; g_fd2[i0 + r0] = dd0 * L2E;
        g_fs2[i0 + r1] = ds1 * L2E; g_fd2[i0 + r1] = dd1 * L2E;
        atomicMax(&g_gmax_o, f2o(dd0 * L2E));
        atomicMax(&g_gmax_o, f2o(dd1 * L2E));
    }
}

// ---------------- kernel 2: warp-specialized fused attention ---------------
// grid 128 (64-row i-tiles), block 512:
//   warps 0-7  consume: 2 row-groups x 4 col-groups, each 32 rows x 32 cols
//   warps 8-15 produce: each owns 8 P-rows; H arrival signaled by
//   cp.async.mbarrier.arrive (NO wait_group in producer critical path)
// 3-STAGE pipeline. Stage block = [sH 128x136 half (34816B) | sP 64x136 half (17408B)]
//   stage s at s*52224;  sDen @156672 (64 f32);  mbF @156928 (3x8);  mbE @156952
#define STG      52224
#define OFF_DEN  156672
#define OFF_MBF  156928
#define OFF_MBE  156952
#define SMEM_MAIN 157056

__global__ __launch_bounds__(512, 1) void k_main(
    const float* __restrict__ adj, float* __restrict__ out)
{
    extern __shared__ char smem[];
    const uint32_t sb = (uint32_t)__cvta_generic_to_shared(smem);
    float* sDen = (float*)(smem + OFF_DEN);
    const uint32_t mbF = sb + OFF_MBF;
    const uint32_t mbE = sb + OFF_MBE;

    const int tid = threadIdx.x;
    const int lane = tid & 31, wid = tid >> 5;
    const int i0 = blockIdx.x * 64;

    if (tid == 0) {
        #pragma unroll
        for (int s = 0; s < 3; s++) {
            mbar_init(mbF + s * 8, 512);   // 256 explicit + 256 cp.async arrives
            mbar_init(mbE + s * 8, 256);
        }
    }
    __syncthreads();

    float C[8][4];

    if (wid >= 8) {
        // ---------------- producer: 8 rows per warp ----------------
        const int p = wid - 8;               // 0..7
        const int pt = tid - 256;            // 0..255
        const float gmax2 = o2f(g_gmax_o);
        float fs[8], m2[8], den[8];
        #pragma unroll
        for (int rr = 0; rr < 8; rr++) {
            float f = g_fs2[i0 + p * 8 + rr];
            fs[rr] = f;
            float sm = f + gmax2;
            m2[rr] = (sm >= 0.f) ? sm : 0.2f * sm;
            den[rr] = 0.f;
        }
        const float* adjB = adj + (size_t)(i0 + p * 8) * NN + (lane << 2);

        uint32_t pe0 = 1, pe1 = 1, pe2 = 1;
        int st = 0;
        for (int jt = 0; jt < 64; jt++) {
            const int j0 = jt << 7;

            // hoist loads (latency overlapped with empty-wait)
            float4 av[8];
            const float* arow = adjB + j0;
            #pragma unroll
            for (int rr = 0; rr < 8; rr++)
                av[rr] = __ldcs((const float4*)(arow + (size_t)rr * NN));
            float4 fd = __ldg((const float4*)(g_fd2 + j0 + (lane << 2)));

            uint32_t pe = (st == 0) ? pe0 : (st == 1) ? pe1 : pe2;
            mbar_wait(mbE + st * 8, pe);
            if (st == 0) pe0 ^= 1; else if (st == 1) pe1 ^= 1; else pe2 ^= 1;

            // async-load H tile into stage st; completion arrives on mbF[st]
            const __half* hsrc = g_hh + (size_t)j0 * FOUT;
            const uint32_t hdst = sb + st * STG;
            #pragma unroll
            for (int l = 0; l < 8; l++) {
                int idx = pt + (l << 8);
                int row = idx >> 4, c8 = idx & 15;
                CP_ASYNC16(hdst + (row * 136 + c8 * 8) * 2, hsrc + row * FOUT + c8 * 8);
            }
            mbar_arrive_cpasync(mbF + st * 8);

            // P tile rows p*8..+8, cols lane*4..+4 -> fp16 smem
            float fdv[4] = {fd.x, fd.y, fd.z, fd.w};
            __half* sPs = (__half*)(smem + st * STG + 34816) + p * 8 * 136 + (lane << 2);
            #pragma unroll
            for (int rr = 0; rr < 8; rr++) {
                float p4[4];
                const float* aa = (const float*)&av[rr];
                #pragma unroll
                for (int u = 0; u < 4; u++) {
                    float s2 = fs[rr] + fdv[u];
                    float t = ((s2 >= 0.f) ? s2 : 0.2f * s2) - m2[rr];
                    float e;
                    asm("ex2.approx.ftz.f32 %0, %1;" : "=f"(e) : "f"(t));
                    p4[u] = (aa[u] > 0.f) ? e : 0.f;
                    den[rr] += p4[u];
                }
                __half2 h01 = __floats2half2_rn(p4[0], p4[1]);
                __half2 h23 = __floats2half2_rn(p4[2], p4[3]);
                uint2 pk; pk.x = *(uint32_t*)&h01; pk.y = *(uint32_t*)&h23;
                *(uint2*)(sPs + rr * 136) = pk;
            }

            mbar_arrive(mbF + st * 8);   // release sP writes
            st = (st == 2) ? 0 : st + 1;
        }
        // reduce denominators across lanes
        #pragma unroll
        for (int rr = 0; rr < 8; rr++) {
            float v = den[rr];
            #pragma unroll
            for (int o = 1; o < 32; o <<= 1) v += __shfl_xor_sync(0xffffffffu, v, o);
            if (lane == 0) sDen[p * 8 + rr] = v;
        }
    } else {
        // ---------------- consumer: 32 rows x 32 cols per warp (2x4 grid) ----
        #pragma unroll
        for (int a = 0; a < 8; a++)
            #pragma unroll
            for (int b = 0; b < 4; b++) C[a][b] = 0.f;

        const int wm = (wid & 1) * 32;    // 2 row-groups of 32
        const int wn = (wid >> 1) * 32;   // 4 col-groups of 32

        uint32_t pf0 = 0, pf1 = 0, pf2 = 0;
        int st = 0;
        for (int jt = 0; jt < 64; jt++) {
            uint32_t pf = (st == 0) ? pf0 : (st == 1) ? pf1 : pf2;
            mbar_wait(mbF + st * 8, pf);
            if (st == 0) pf0 ^= 1; else if (st == 1) pf1 ^= 1; else pf2 ^= 1;

            const uint32_t aB = sb + st * STG + 34816 +
                ((wm + (lane & 15)) * 136 + ((lane >> 4) << 3)) * 2;
            const uint32_t bB = sb + st * STG +
                ((lane & 15) * 136 + wn + ((lane >> 4) << 3)) * 2;

            #pragma unroll
            for (int kk = 0; kk < 8; kk++) {
                uint32_t a0[4], a1[4];
                asm volatile("ldmatrix.sync.aligned.m8n8.x4.shared.b16 {%0,%1,%2,%3},[%4];\n"
                             : "=r"(a0[0]), "=r"(a0[1]), "=r"(a0[2]), "=r"(a0[3])
                             : "r"(aB + kk * 32));
                asm volatile("ldmatrix.sync.aligned.m8n8.x4.shared.b16 {%0,%1,%2,%3},[%4];\n"
                             : "=r"(a1[0]), "=r"(a1[1]), "=r"(a1[2]), "=r"(a1[3])
                             : "r"(aB + 16 * 272 + kk * 32));
                #pragma unroll
                for (int nt = 0; nt < 2; nt++) {
                    uint32_t b0, b1, b2, b3;
                    asm volatile("ldmatrix.sync.aligned.m8n8.x4.trans.shared.b16 {%0,%1,%2,%3},[%4];\n"
                                 : "=r"(b0), "=r"(b1), "=r"(b2), "=r"(b3)
                                 : "r"(bB + kk * 16 * 272 + nt * 32));
                    MMA16816(C[nt*2][0], C[nt*2][1], C[nt*2][2], C[nt*2][3],
                             a0[0], a0[1], a0[2], a0[3], b0, b1);
                    MMA16816(C[nt*2+1][0], C[nt*2+1][1], C[nt*2+1][2], C[nt*2+1][3],
                             a0[0], a0[1], a0[2], a0[3], b2, b3);
                    MMA16816(C[4+nt*2][0], C[4+nt*2][1], C[4+nt*2][2], C[4+nt*2][3],
                             a1[0], a1[1], a1[2], a1[3], b0, b1);
                    MMA16816(C[4+nt*2+1][0], C[4+nt*2+1][1], C[4+nt*2+1][2], C[4+nt*2+1][3],
                             a1[0], a1[1], a1[2], a1[3], b2, b3);
                }
            }
            mbar_arrive(mbE + st * 8);
            st = (st == 2) ? 0 : st + 1;
        }
    }

    __syncthreads();

    if (wid < 8) {
        const int wm = (wid & 1) * 32;
        const int wn = (wid >> 1) * 32;
        const int g = lane >> 2, q = lane & 3;
        #pragma unroll
        for (int mt = 0; mt < 2; mt++) {
            const int r0 = wm + mt * 16 + g;
            const int r1 = r0 + 8;
            const float inv0 = 1.f / sDen[r0];
            const float inv1 = 1.f / sDen[r1];
            #pragma unroll
            for (int nt = 0; nt < 4; nt++) {
                const float* frag = C[mt * 4 + nt];
                int col = wn + nt * 8 + q * 2;
                float* o0 = &out[(size_t)(i0 + r0) * FOUT + col];
                o0[0] = frag[0] * inv0;
                o0[1] = frag[1] * inv0;
                float* o1 = &out[(size_t)(i0 + r1) * FOUT + col];
                o1[0] = frag[2] * inv1;
                o1[1] = frag[3] * inv1;
            }
        }
    }
}

// ---------------- launcher ----------------
extern "C" void kernel_launch(void* const* d_in, const int* in_sizes, int n_in,
                              void* d_out, int out_size)
{
    const float* x     = (const float*)d_in[0];
    const float* adj   = (const float*)d_in[1];
    const float* W     = (const float*)d_in[2];
    const float* a_src = (const float*)d_in[3];
    const float* a_dst = (const float*)d_in[4];
    float* out = (float*)d_out;

    cudaFuncSetAttribute(k_gemm, cudaFuncAttributeMaxDynamicSharedMemorySize, SMEM_GEMM);
    cudaFuncSetAttribute(k_main, cudaFuncAttributeMaxDynamicSharedMemorySize, SMEM_MAIN);

    k_gemm<<<128, 128, SMEM_GEMM>>>(x, W, a_src, a_dst);
    k_main<<<128, 512, SMEM_MAIN>>>(adj, out);
}